// round 8
// baseline (speedup 1.0000x reference)
#include <cuda_runtime.h>
#include <cuda_bf16.h>
#include <math.h>

#define NN 100000
#define EE 1600000
#define FIN 128
#define FOUT 32
#define ALPHA 0.2f

#define RB 64          // rows per gemm block
#define XS_STRIDE 132  // 128 + 4 pad

// Scratch (__device__ globals; no cudaMalloc allowed)
__device__ __align__(16) float g_Wx[(size_t)NN * FOUT];   // 12.8 MB
__device__ float g_as[NN];
__device__ float g_ad[NN];
__device__ int   g_cnt[NN];
__device__ int   g_rowptr[NN + 1];
__device__ int   g_wpos[NN];
__device__ int   g_edst[EE];

__device__ __forceinline__ float leaky(float v) {
    return v >= 0.0f ? v : ALPHA * v;
}

// ---------------------------------------------------------------------------
// K0: zero counters (tiny; must complete before K1's fused histogram)
// ---------------------------------------------------------------------------
__global__ void k_zero(int n) {
    int i = blockIdx.x * blockDim.x + threadIdx.x;
    if (i < n) g_cnt[i] = 0;
}

// ---------------------------------------------------------------------------
// K1: register-blocked Wx = x @ W + alpha projections + FUSED src histogram.
// The histogram atomics (latency-bound, LSU/LTS) are issued up front and
// drain while the FMA-bound GEMM computes — nearly free.
// ---------------------------------------------------------------------------
__global__ __launch_bounds__(256) void k_gemm_alpha_hist(
    const float* __restrict__ x, const float* __restrict__ W,
    const float* __restrict__ a, const int* __restrict__ ei, int n, int E)
{
    __shared__ float xs[RB * XS_STRIDE];   // 33.8 KB
    __shared__ float av[2 * FOUT];

    int t = threadIdx.x;
    int row0 = blockIdx.x * RB;

    if (t < 2 * FOUT) av[t] = a[t];

    // stage x tile: 64 rows x 32 float4, 8 per thread
    for (int i = t; i < RB * (FIN / 4); i += 256) {
        int r = i >> 5;
        int c = i & 31;
        int row = row0 + r;
        float4 v = (row < n)
            ? reinterpret_cast<const float4*>(x + (size_t)row * FIN)[c]
            : make_float4(0.f, 0.f, 0.f, 0.f);
        *reinterpret_cast<float4*>(&xs[r * XS_STRIDE + c * 4]) = v;
    }

    // fused histogram: grid-stride over edges (atomics overlap with FMA below)
    {
        int stride = gridDim.x * 256;
        for (int e = blockIdx.x * 256 + t; e < E; e += stride)
            atomicAdd(&g_cnt[ei[e]], 1);
    }
    __syncthreads();

    int lane = t & 31;
    int warp = t >> 5;
    int rr = warp * 8 + (lane >> 2);   // local row 0..63
    int cg = lane & 3;                 // col group: cols cg*8 .. cg*8+7

    float acc[8];
#pragma unroll
    for (int j = 0; j < 8; j++) acc[j] = 0.0f;

    const float4* W4 = reinterpret_cast<const float4*>(W);
    const float* xrow = &xs[rr * XS_STRIDE];

#pragma unroll 16
    for (int k = 0; k < FIN; k++) {
        float xv = xrow[k];
        float4 w0 = __ldg(&W4[k * 8 + cg * 2]);
        float4 w1 = __ldg(&W4[k * 8 + cg * 2 + 1]);
        acc[0] = fmaf(xv, w0.x, acc[0]);
        acc[1] = fmaf(xv, w0.y, acc[1]);
        acc[2] = fmaf(xv, w0.z, acc[2]);
        acc[3] = fmaf(xv, w0.w, acc[3]);
        acc[4] = fmaf(xv, w1.x, acc[4]);
        acc[5] = fmaf(xv, w1.y, acc[5]);
        acc[6] = fmaf(xv, w1.z, acc[6]);
        acc[7] = fmaf(xv, w1.w, acc[7]);
    }

    int grow = row0 + rr;
    if (grow < n) {
        float4* wp = reinterpret_cast<float4*>(g_Wx + (size_t)grow * FOUT + cg * 8);
        wp[0] = make_float4(acc[0], acc[1], acc[2], acc[3]);
        wp[1] = make_float4(acc[4], acc[5], acc[6], acc[7]);

        float vs = 0.f, vd = 0.f;
#pragma unroll
        for (int j = 0; j < 8; j++) {
            vs = fmaf(acc[j], av[cg * 8 + j], vs);
            vd = fmaf(acc[j], av[FOUT + cg * 8 + j], vd);
        }
        vs += __shfl_xor_sync(0xFFFFFFFFu, vs, 1);
        vs += __shfl_xor_sync(0xFFFFFFFFu, vs, 2);
        vd += __shfl_xor_sync(0xFFFFFFFFu, vd, 1);
        vd += __shfl_xor_sync(0xFFFFFFFFu, vd, 2);
        if (cg == 0) {
            g_as[grow] = vs;
            g_ad[grow] = vd;
        }
    }
}

// ---------------------------------------------------------------------------
// K2: single-block exclusive scan of g_cnt -> g_rowptr / g_wpos
// ---------------------------------------------------------------------------
__global__ __launch_bounds__(1024) void k_scan(int n, int E) {
    __shared__ int sm[1024];
    int t = threadIdx.x;
    int ch = (n + 1023) / 1024;
    int lo = t * ch;
    int hi = min(lo + ch, n);

    int sum = 0;
    for (int i = lo; i < hi; i++) sum += g_cnt[i];

    sm[t] = sum;
    __syncthreads();
#pragma unroll
    for (int off = 1; off < 1024; off <<= 1) {
        int v = (t >= off) ? sm[t - off] : 0;
        __syncthreads();
        sm[t] += v;
        __syncthreads();
    }
    int run = sm[t] - sum;   // exclusive prefix of this chunk

    for (int i = lo; i < hi; i++) {
        g_rowptr[i] = run;
        g_wpos[i] = run;
        run += g_cnt[i];
    }
    if (t == 0) g_rowptr[n] = E;
}

// ---------------------------------------------------------------------------
// K3: scatter dst indices into CSR slots
// ---------------------------------------------------------------------------
__global__ __launch_bounds__(256) void k_scatter(const int* __restrict__ ei, int E) {
    int e = blockIdx.x * blockDim.x + threadIdx.x;
    if (e >= E) return;
    int s = ei[e];
    int d = ei[E + e];
    int pos = atomicAdd(&g_wpos[s], 1);
    g_edst[pos] = d;
}

// ---------------------------------------------------------------------------
// K4: fused softmax + aggregation + ELU, one pass (shift-invariant softmax).
// One warp per node: 4 edges in parallel (8-lane subgroups), each lane holds
// a float4 of the 32 features. (Measured-good round-4/7 form, unchanged.)
// ---------------------------------------------------------------------------
__global__ __launch_bounds__(256) void k_agg(float* __restrict__ out, int n) {
    int u = (blockIdx.x * blockDim.x + threadIdx.x) >> 5;
    int lane = threadIdx.x & 31;
    if (u >= n) return;

    int beg = g_rowptr[u];
    int end = g_rowptr[u + 1];
    float4* op = reinterpret_cast<float4*>(out + (size_t)u * FOUT);

    if (beg == end) {            // isolated node: h = 0 -> elu(0) = 0
        if (lane < 8) op[lane] = make_float4(0.f, 0.f, 0.f, 0.f);
        return;
    }

    float a_s = g_as[u];
    int sub = lane >> 3;         // edge subgroup 0..3
    int fl  = lane & 7;          // feature float4 index 0..7

    float4 acc = make_float4(0.f, 0.f, 0.f, 0.f);
    float ssum = 0.0f;
    const float4* Wx4 = reinterpret_cast<const float4*>(g_Wx);

    for (int i = beg + sub; i < end; i += 4) {
        int d = g_edst[i];
        float ev = __expf(leaky(a_s + g_ad[d]));
        float4 w = Wx4[(size_t)d * 8 + fl];
        acc.x = fmaf(ev, w.x, acc.x);
        acc.y = fmaf(ev, w.y, acc.y);
        acc.z = fmaf(ev, w.z, acc.z);
        acc.w = fmaf(ev, w.w, acc.w);
        ssum += ev;
    }

#pragma unroll
    for (int o = 8; o <= 16; o <<= 1) {
        acc.x += __shfl_xor_sync(0xFFFFFFFFu, acc.x, o);
        acc.y += __shfl_xor_sync(0xFFFFFFFFu, acc.y, o);
        acc.z += __shfl_xor_sync(0xFFFFFFFFu, acc.z, o);
        acc.w += __shfl_xor_sync(0xFFFFFFFFu, acc.w, o);
        ssum  += __shfl_xor_sync(0xFFFFFFFFu, ssum, o);
    }

    if (lane < 8) {
        float inv = 1.0f / ssum;
        float v;
        float4 r;
        v = acc.x * inv; r.x = v > 0.f ? v : expm1f(v);
        v = acc.y * inv; r.y = v > 0.f ? v : expm1f(v);
        v = acc.z * inv; r.z = v > 0.f ? v : expm1f(v);
        v = acc.w * inv; r.w = v > 0.f ? v : expm1f(v);
        op[fl] = r;
    }
}

// ---------------------------------------------------------------------------
extern "C" void kernel_launch(void* const* d_in, const int* in_sizes, int n_in,
                              void* d_out, int out_size)
{
    const float* x  = (const float*)d_in[0];   // (N, 128)
    const float* W  = (const float*)d_in[1];   // (128, 32)
    const float* a  = (const float*)d_in[2];   // (64, 1)
    const int*   ei = (const int*)d_in[3];     // (2, E) int32
    float* out = (float*)d_out;                // (N, 32)

    const int n = in_sizes[0] / FIN;
    const int E = in_sizes[3] / 2;

    k_zero<<<(n + 255) / 256, 256>>>(n);
    k_gemm_alpha_hist<<<(n + RB - 1) / RB, 256>>>(x, W, a, ei, n, E);
    k_scan<<<1, 1024>>>(n, E);
    k_scatter<<<(E + 255) / 256, 256>>>(ei, E);
    k_agg<<<(n * 32 + 255) / 256, 256>>>(out, n);
}

// round 9
// speedup vs baseline: 2.0183x; 2.0183x over previous
#include <cuda_runtime.h>
#include <cuda_bf16.h>
#include <math.h>

#define NN 100000
#define EE 1600000
#define FIN 128
#define FOUT 32
#define ALPHA 0.2f

#define SCAN_CH 512
#define SCAN_BLOCKS ((NN + SCAN_CH - 1) / SCAN_CH)   // 196

#define RB 64          // rows per gemm block
#define XS_STRIDE 132  // 128 + 4 pad

// Scratch (__device__ globals; no cudaMalloc allowed)
__device__ __align__(16) float g_Wx[(size_t)NN * FOUT];   // 12.8 MB
__device__ float g_as[NN];
__device__ float g_ad[NN];
__device__ int   g_cnt[NN];
__device__ int   g_rowptr[NN + 1];
__device__ int   g_wpos[NN];
__device__ int   g_bsum[SCAN_BLOCKS];
__device__ int   g_boff[SCAN_BLOCKS];
__device__ int   g_edst[EE];

__device__ __forceinline__ float leaky(float v) {
    return v >= 0.0f ? v : ALPHA * v;
}

// ---------------------------------------------------------------------------
// K1: register-blocked Wx = x @ W + alpha projections + folded counter init.
// (Measured-good round-7 form, unchanged.)
// ---------------------------------------------------------------------------
__global__ __launch_bounds__(256) void k_gemm_alpha(
    const float* __restrict__ x, const float* __restrict__ W,
    const float* __restrict__ a, int n)
{
    __shared__ float xs[RB * XS_STRIDE];   // 33.8 KB
    __shared__ float av[2 * FOUT];

    int t = threadIdx.x;
    int row0 = blockIdx.x * RB;

    int gtid = blockIdx.x * 256 + t;
    if (gtid < n) g_cnt[gtid] = 0;

    if (t < 2 * FOUT) av[t] = a[t];

    for (int i = t; i < RB * (FIN / 4); i += 256) {
        int r = i >> 5;
        int c = i & 31;
        int row = row0 + r;
        float4 v = (row < n)
            ? reinterpret_cast<const float4*>(x + (size_t)row * FIN)[c]
            : make_float4(0.f, 0.f, 0.f, 0.f);
        *reinterpret_cast<float4*>(&xs[r * XS_STRIDE + c * 4]) = v;
    }
    __syncthreads();

    int lane = t & 31;
    int warp = t >> 5;
    int rr = warp * 8 + (lane >> 2);   // local row 0..63
    int cg = lane & 3;                 // col group

    float acc[8];
#pragma unroll
    for (int j = 0; j < 8; j++) acc[j] = 0.0f;

    const float4* W4 = reinterpret_cast<const float4*>(W);
    const float* xrow = &xs[rr * XS_STRIDE];

#pragma unroll 16
    for (int k = 0; k < FIN; k++) {
        float xv = xrow[k];
        float4 w0 = __ldg(&W4[k * 8 + cg * 2]);
        float4 w1 = __ldg(&W4[k * 8 + cg * 2 + 1]);
        acc[0] = fmaf(xv, w0.x, acc[0]);
        acc[1] = fmaf(xv, w0.y, acc[1]);
        acc[2] = fmaf(xv, w0.z, acc[2]);
        acc[3] = fmaf(xv, w0.w, acc[3]);
        acc[4] = fmaf(xv, w1.x, acc[4]);
        acc[5] = fmaf(xv, w1.y, acc[5]);
        acc[6] = fmaf(xv, w1.z, acc[6]);
        acc[7] = fmaf(xv, w1.w, acc[7]);
    }

    int grow = row0 + rr;
    if (grow < n) {
        float4* wp = reinterpret_cast<float4*>(g_Wx + (size_t)grow * FOUT + cg * 8);
        wp[0] = make_float4(acc[0], acc[1], acc[2], acc[3]);
        wp[1] = make_float4(acc[4], acc[5], acc[6], acc[7]);

        float vs = 0.f, vd = 0.f;
#pragma unroll
        for (int j = 0; j < 8; j++) {
            vs = fmaf(acc[j], av[cg * 8 + j], vs);
            vd = fmaf(acc[j], av[FOUT + cg * 8 + j], vd);
        }
        vs += __shfl_xor_sync(0xFFFFFFFFu, vs, 1);
        vs += __shfl_xor_sync(0xFFFFFFFFu, vs, 2);
        vd += __shfl_xor_sync(0xFFFFFFFFu, vd, 1);
        vd += __shfl_xor_sync(0xFFFFFFFFu, vd, 2);
        if (cg == 0) {
            g_as[grow] = vs;
            g_ad[grow] = vd;
        }
    }
}

// ---------------------------------------------------------------------------
// K2: histogram of src — 4 edges per thread (int4 load), 4 independent atomics
// ---------------------------------------------------------------------------
__global__ __launch_bounds__(256) void k_hist(const int* __restrict__ ei, int E) {
    int b = blockIdx.x * blockDim.x + threadIdx.x;   // quad index
    int e0 = b * 4;
    if (e0 + 3 < E) {
        int4 s = *reinterpret_cast<const int4*>(ei + e0);
        atomicAdd(&g_cnt[s.x], 1);
        atomicAdd(&g_cnt[s.y], 1);
        atomicAdd(&g_cnt[s.z], 1);
        atomicAdd(&g_cnt[s.w], 1);
    } else {
        for (int e = e0; e < E; e++) atomicAdd(&g_cnt[ei[e]], 1);
    }
}

// ---------------------------------------------------------------------------
// K3a/b/c: two-level exclusive scan of g_cnt -> g_rowptr (and g_wpos copy)
// (Measured-good multi-block form — single-block scan was a 100+us trap.)
// ---------------------------------------------------------------------------
__global__ __launch_bounds__(SCAN_CH) void k_scan1(int n) {
    __shared__ int sm[SCAN_CH];
    int idx = blockIdx.x * SCAN_CH + threadIdx.x;
    sm[threadIdx.x] = (idx < n) ? g_cnt[idx] : 0;
    __syncthreads();
    for (int off = SCAN_CH / 2; off > 0; off >>= 1) {
        if (threadIdx.x < off) sm[threadIdx.x] += sm[threadIdx.x + off];
        __syncthreads();
    }
    if (threadIdx.x == 0) g_bsum[blockIdx.x] = sm[0];
}

__global__ __launch_bounds__(256) void k_scan2(int nb, int n, int E) {
    __shared__ int sm[256];
    int tid = threadIdx.x;
    int v = (tid < nb) ? g_bsum[tid] : 0;
    sm[tid] = v;
    __syncthreads();
    for (int off = 1; off < 256; off <<= 1) {
        int t = (tid >= off) ? sm[tid - off] : 0;
        __syncthreads();
        sm[tid] += t;
        __syncthreads();
    }
    if (tid < nb) g_boff[tid] = sm[tid] - v;   // exclusive
    if (tid == 0) g_rowptr[n] = E;
}

__global__ __launch_bounds__(SCAN_CH) void k_scan3(int n) {
    __shared__ int sm[SCAN_CH];
    int tid = threadIdx.x;
    int idx = blockIdx.x * SCAN_CH + tid;
    int v = (idx < n) ? g_cnt[idx] : 0;
    sm[tid] = v;
    __syncthreads();
    for (int off = 1; off < SCAN_CH; off <<= 1) {
        int t = (tid >= off) ? sm[tid - off] : 0;
        __syncthreads();
        sm[tid] += t;
        __syncthreads();
    }
    if (idx < n) {
        int ex = g_boff[blockIdx.x] + sm[tid] - v;
        g_rowptr[idx] = ex;
        g_wpos[idx] = ex;
    }
}

// ---------------------------------------------------------------------------
// K4: scatter dst into CSR slots — 4 edges per thread (int4 loads) for MLP
// ---------------------------------------------------------------------------
__global__ __launch_bounds__(256) void k_scatter(const int* __restrict__ ei, int E) {
    int b = blockIdx.x * blockDim.x + threadIdx.x;   // quad index
    int e0 = b * 4;
    if (e0 + 3 < E) {
        int4 s = *reinterpret_cast<const int4*>(ei + e0);
        int4 d = *reinterpret_cast<const int4*>(ei + E + e0);
        int p0 = atomicAdd(&g_wpos[s.x], 1);
        int p1 = atomicAdd(&g_wpos[s.y], 1);
        int p2 = atomicAdd(&g_wpos[s.z], 1);
        int p3 = atomicAdd(&g_wpos[s.w], 1);
        g_edst[p0] = d.x;
        g_edst[p1] = d.y;
        g_edst[p2] = d.z;
        g_edst[p3] = d.w;
    } else {
        for (int e = e0; e < E; e++) {
            int pos = atomicAdd(&g_wpos[ei[e]], 1);
            g_edst[pos] = ei[E + e];
        }
    }
}

// ---------------------------------------------------------------------------
// K5: fused softmax + aggregation + ELU (measured-good round-4/7 form).
// ---------------------------------------------------------------------------
__global__ __launch_bounds__(256) void k_agg(float* __restrict__ out, int n) {
    int u = (blockIdx.x * blockDim.x + threadIdx.x) >> 5;
    int lane = threadIdx.x & 31;
    if (u >= n) return;

    int beg = g_rowptr[u];
    int end = g_rowptr[u + 1];
    float4* op = reinterpret_cast<float4*>(out + (size_t)u * FOUT);

    if (beg == end) {
        if (lane < 8) op[lane] = make_float4(0.f, 0.f, 0.f, 0.f);
        return;
    }

    float a_s = g_as[u];
    int sub = lane >> 3;
    int fl  = lane & 7;

    float4 acc = make_float4(0.f, 0.f, 0.f, 0.f);
    float ssum = 0.0f;
    const float4* Wx4 = reinterpret_cast<const float4*>(g_Wx);

    for (int i = beg + sub; i < end; i += 4) {
        int d = g_edst[i];
        float ev = __expf(leaky(a_s + g_ad[d]));
        float4 w = Wx4[(size_t)d * 8 + fl];
        acc.x = fmaf(ev, w.x, acc.x);
        acc.y = fmaf(ev, w.y, acc.y);
        acc.z = fmaf(ev, w.z, acc.z);
        acc.w = fmaf(ev, w.w, acc.w);
        ssum += ev;
    }

#pragma unroll
    for (int o = 8; o <= 16; o <<= 1) {
        acc.x += __shfl_xor_sync(0xFFFFFFFFu, acc.x, o);
        acc.y += __shfl_xor_sync(0xFFFFFFFFu, acc.y, o);
        acc.z += __shfl_xor_sync(0xFFFFFFFFu, acc.z, o);
        acc.w += __shfl_xor_sync(0xFFFFFFFFu, acc.w, o);
        ssum  += __shfl_xor_sync(0xFFFFFFFFu, ssum, o);
    }

    if (lane < 8) {
        float inv = 1.0f / ssum;
        float v;
        float4 r;
        v = acc.x * inv; r.x = v > 0.f ? v : expm1f(v);
        v = acc.y * inv; r.y = v > 0.f ? v : expm1f(v);
        v = acc.z * inv; r.z = v > 0.f ? v : expm1f(v);
        v = acc.w * inv; r.w = v > 0.f ? v : expm1f(v);
        op[fl] = r;
    }
}

// ---------------------------------------------------------------------------
extern "C" void kernel_launch(void* const* d_in, const int* in_sizes, int n_in,
                              void* d_out, int out_size)
{
    const float* x  = (const float*)d_in[0];   // (N, 128)
    const float* W  = (const float*)d_in[1];   // (128, 32)
    const float* a  = (const float*)d_in[2];   // (64, 1)
    const int*   ei = (const int*)d_in[3];     // (2, E) int32
    float* out = (float*)d_out;                // (N, 32)

    const int n = in_sizes[0] / FIN;
    const int E = in_sizes[3] / 2;
    const int nb = (n + SCAN_CH - 1) / SCAN_CH;
    const int quads = (E + 3) / 4;

    k_gemm_alpha<<<(n + RB - 1) / RB, 256>>>(x, W, a, n);
    k_hist<<<(quads + 255) / 256, 256>>>(ei, E);
    k_scan1<<<nb, SCAN_CH>>>(n);
    k_scan2<<<1, 256>>>(nb, n, E);
    k_scan3<<<nb, SCAN_CH>>>(n);
    k_scatter<<<(quads + 255) / 256, 256>>>(ei, E);
    k_agg<<<(n * 32 + 255) / 256, 256>>>(out, n);
}

// round 11
// speedup vs baseline: 2.0762x; 1.0287x over previous
#include <cuda_runtime.h>
#include <cuda_bf16.h>
#include <math.h>

#define NN 100000
#define EE 1600000
#define FIN 128
#define FOUT 32
#define ALPHA 0.2f

#define SCAN_CH 512
#define SCAN_BLOCKS ((NN + SCAN_CH - 1) / SCAN_CH)   // 196

#define RB 64          // rows per gemm block
#define XS_STRIDE 132  // 128 + 4 pad

// Scratch (__device__ globals; no cudaMalloc allowed)
__device__ __align__(16) float g_Wx[(size_t)NN * FOUT];   // 12.8 MB
__device__ float g_as[NN];
__device__ float g_ad[NN];
__device__ int   g_cnt[NN];
__device__ int   g_rowptr[NN + 1];
__device__ int   g_wpos[NN];
__device__ int   g_bsum[SCAN_BLOCKS];
__device__ int   g_boff[SCAN_BLOCKS];
__device__ int   g_edst[EE];

__device__ __forceinline__ float leaky(float v) {
    return v >= 0.0f ? v : ALPHA * v;
}

// ---------------------------------------------------------------------------
// K1: register-blocked Wx = x @ W + alpha projections + folded counter init.
// (Measured-good round-7 form, unchanged.)
// ---------------------------------------------------------------------------
__global__ __launch_bounds__(256) void k_gemm_alpha(
    const float* __restrict__ x, const float* __restrict__ W,
    const float* __restrict__ a, int n)
{
    __shared__ float xs[RB * XS_STRIDE];   // 33.8 KB
    __shared__ float av[2 * FOUT];

    int t = threadIdx.x;
    int row0 = blockIdx.x * RB;

    int gtid = blockIdx.x * 256 + t;
    if (gtid < n) g_cnt[gtid] = 0;

    if (t < 2 * FOUT) av[t] = a[t];

    for (int i = t; i < RB * (FIN / 4); i += 256) {
        int r = i >> 5;
        int c = i & 31;
        int row = row0 + r;
        float4 v = (row < n)
            ? reinterpret_cast<const float4*>(x + (size_t)row * FIN)[c]
            : make_float4(0.f, 0.f, 0.f, 0.f);
        *reinterpret_cast<float4*>(&xs[r * XS_STRIDE + c * 4]) = v;
    }
    __syncthreads();

    int lane = t & 31;
    int warp = t >> 5;
    int rr = warp * 8 + (lane >> 2);   // local row 0..63
    int cg = lane & 3;                 // col group

    float acc[8];
#pragma unroll
    for (int j = 0; j < 8; j++) acc[j] = 0.0f;

    const float4* W4 = reinterpret_cast<const float4*>(W);
    const float* xrow = &xs[rr * XS_STRIDE];

#pragma unroll 16
    for (int k = 0; k < FIN; k++) {
        float xv = xrow[k];
        float4 w0 = __ldg(&W4[k * 8 + cg * 2]);
        float4 w1 = __ldg(&W4[k * 8 + cg * 2 + 1]);
        acc[0] = fmaf(xv, w0.x, acc[0]);
        acc[1] = fmaf(xv, w0.y, acc[1]);
        acc[2] = fmaf(xv, w0.z, acc[2]);
        acc[3] = fmaf(xv, w0.w, acc[3]);
        acc[4] = fmaf(xv, w1.x, acc[4]);
        acc[5] = fmaf(xv, w1.y, acc[5]);
        acc[6] = fmaf(xv, w1.z, acc[6]);
        acc[7] = fmaf(xv, w1.w, acc[7]);
    }

    int grow = row0 + rr;
    if (grow < n) {
        float4* wp = reinterpret_cast<float4*>(g_Wx + (size_t)grow * FOUT + cg * 8);
        wp[0] = make_float4(acc[0], acc[1], acc[2], acc[3]);
        wp[1] = make_float4(acc[4], acc[5], acc[6], acc[7]);

        float vs = 0.f, vd = 0.f;
#pragma unroll
        for (int j = 0; j < 8; j++) {
            vs = fmaf(acc[j], av[cg * 8 + j], vs);
            vd = fmaf(acc[j], av[FOUT + cg * 8 + j], vd);
        }
        vs += __shfl_xor_sync(0xFFFFFFFFu, vs, 1);
        vs += __shfl_xor_sync(0xFFFFFFFFu, vs, 2);
        vd += __shfl_xor_sync(0xFFFFFFFFu, vd, 1);
        vd += __shfl_xor_sync(0xFFFFFFFFu, vd, 2);
        if (cg == 0) {
            g_as[grow] = vs;
            g_ad[grow] = vd;
        }
    }
}

// ---------------------------------------------------------------------------
// K2: histogram of src — 4 edges per thread (int4 load)
// ---------------------------------------------------------------------------
__global__ __launch_bounds__(256) void k_hist(const int* __restrict__ ei, int E) {
    int b = blockIdx.x * blockDim.x + threadIdx.x;
    int e0 = b * 4;
    if (e0 + 3 < E) {
        int4 s = *reinterpret_cast<const int4*>(ei + e0);
        atomicAdd(&g_cnt[s.x], 1);
        atomicAdd(&g_cnt[s.y], 1);
        atomicAdd(&g_cnt[s.z], 1);
        atomicAdd(&g_cnt[s.w], 1);
    } else {
        for (int e = e0; e < E; e++) atomicAdd(&g_cnt[ei[e]], 1);
    }
}

// ---------------------------------------------------------------------------
// K3a/b/c: two-level exclusive scan of g_cnt -> g_rowptr (and g_wpos copy)
// ---------------------------------------------------------------------------
__global__ __launch_bounds__(SCAN_CH) void k_scan1(int n) {
    __shared__ int sm[SCAN_CH];
    int idx = blockIdx.x * SCAN_CH + threadIdx.x;
    sm[threadIdx.x] = (idx < n) ? g_cnt[idx] : 0;
    __syncthreads();
    for (int off = SCAN_CH / 2; off > 0; off >>= 1) {
        if (threadIdx.x < off) sm[threadIdx.x] += sm[threadIdx.x + off];
        __syncthreads();
    }
    if (threadIdx.x == 0) g_bsum[blockIdx.x] = sm[0];
}

__global__ __launch_bounds__(256) void k_scan2(int nb, int n, int E) {
    __shared__ int sm[256];
    int tid = threadIdx.x;
    int v = (tid < nb) ? g_bsum[tid] : 0;
    sm[tid] = v;
    __syncthreads();
    for (int off = 1; off < 256; off <<= 1) {
        int t = (tid >= off) ? sm[tid - off] : 0;
        __syncthreads();
        sm[tid] += t;
        __syncthreads();
    }
    if (tid < nb) g_boff[tid] = sm[tid] - v;   // exclusive
    if (tid == 0) g_rowptr[n] = E;
}

__global__ __launch_bounds__(SCAN_CH) void k_scan3(int n) {
    __shared__ int sm[SCAN_CH];
    int tid = threadIdx.x;
    int idx = blockIdx.x * SCAN_CH + tid;
    int v = (idx < n) ? g_cnt[idx] : 0;
    sm[tid] = v;
    __syncthreads();
    for (int off = 1; off < SCAN_CH; off <<= 1) {
        int t = (tid >= off) ? sm[tid - off] : 0;
        __syncthreads();
        sm[tid] += t;
        __syncthreads();
    }
    if (idx < n) {
        int ex = g_boff[blockIdx.x] + sm[tid] - v;
        g_rowptr[idx] = ex;
        g_wpos[idx] = ex;
    }
}

// ---------------------------------------------------------------------------
// K4: scatter dst into CSR slots — 4 edges per thread (int4 loads)
// ---------------------------------------------------------------------------
__global__ __launch_bounds__(256) void k_scatter(const int* __restrict__ ei, int E) {
    int b = blockIdx.x * blockDim.x + threadIdx.x;
    int e0 = b * 4;
    if (e0 + 3 < E) {
        int4 s = *reinterpret_cast<const int4*>(ei + e0);
        int4 d = *reinterpret_cast<const int4*>(ei + E + e0);
        int p0 = atomicAdd(&g_wpos[s.x], 1);
        int p1 = atomicAdd(&g_wpos[s.y], 1);
        int p2 = atomicAdd(&g_wpos[s.z], 1);
        int p3 = atomicAdd(&g_wpos[s.w], 1);
        g_edst[p0] = d.x;
        g_edst[p1] = d.y;
        g_edst[p2] = d.z;
        g_edst[p3] = d.w;
    } else {
        for (int e = e0; e < E; e++) {
            int pos = atomicAdd(&g_wpos[ei[e]], 1);
            g_edst[pos] = ei[E + e];
        }
    }
}

// ---------------------------------------------------------------------------
// K5: fused softmax + aggregation + ELU, two-phase with WARP-UNIFORM shfls.
//  Phase A (per 32-edge chunk): coalesced edst load, one expf per edge,
//  per-lane ssum. Tail lanes hold d=0, ev=0 (safe zero contribution).
//  Phase B: k0 loop bound depends only on cnt (warp-uniform); each 8-lane
//  subgroup handles edges k0+sub and k0+sub+4 via register shfl.idx.
//  Out-of-range k reads a tail lane -> ev=0, d=0 -> contributes nothing.
// ---------------------------------------------------------------------------
__global__ __launch_bounds__(256) void k_agg(float* __restrict__ out, int n) {
    int u = (blockIdx.x * blockDim.x + threadIdx.x) >> 5;
    int lane = threadIdx.x & 31;
    if (u >= n) return;

    int beg = g_rowptr[u];
    int end = g_rowptr[u + 1];
    float4* op = reinterpret_cast<float4*>(out + (size_t)u * FOUT);

    if (beg == end) {            // isolated node: h = 0 -> elu(0) = 0
        if (lane < 8) op[lane] = make_float4(0.f, 0.f, 0.f, 0.f);
        return;
    }

    float a_s = g_as[u];
    int sub = lane >> 3;         // edge subgroup 0..3
    int fl  = lane & 7;          // feature float4 index 0..7

    float4 acc = make_float4(0.f, 0.f, 0.f, 0.f);
    float ssum = 0.0f;
    const float4* Wx4 = reinterpret_cast<const float4*>(g_Wx);

    for (int chunk = beg; chunk < end; chunk += 32) {
        int i = chunk + lane;
        int cnt = min(32, end - chunk);   // warp-uniform

        // Phase A: coalesced edge load + score (one expf per edge)
        int d_l = 0;
        float ev_l = 0.0f;
        if (i < end) {
            d_l = g_edst[i];
            ev_l = __expf(leaky(a_s + g_ad[d_l]));
        }
        ssum += ev_l;

        // Phase B: uniform k0 loop; subgroup handles k0+sub and k0+sub+4.
        for (int k0 = 0; k0 < cnt; k0 += 8) {
            int   ka = k0 + sub;         // <= 27
            int   kb = ka + 4;           // <= 31
            int   da = __shfl_sync(0xFFFFFFFFu, d_l, ka);
            float ea = __shfl_sync(0xFFFFFFFFu, ev_l, ka);
            int   db = __shfl_sync(0xFFFFFFFFu, d_l, kb);
            float eb = __shfl_sync(0xFFFFFFFFu, ev_l, kb);
            float4 wa = Wx4[(size_t)da * 8 + fl];
            float4 wb = Wx4[(size_t)db * 8 + fl];
            acc.x = fmaf(ea, wa.x, fmaf(eb, wb.x, acc.x));
            acc.y = fmaf(ea, wa.y, fmaf(eb, wb.y, acc.y));
            acc.z = fmaf(ea, wa.z, fmaf(eb, wb.z, acc.z));
            acc.w = fmaf(ea, wa.w, fmaf(eb, wb.w, acc.w));
        }
    }

    // acc: reduce across subgroups (lanes sharing fl); ssum: full warp reduce
#pragma unroll
    for (int o = 8; o <= 16; o <<= 1) {
        acc.x += __shfl_xor_sync(0xFFFFFFFFu, acc.x, o);
        acc.y += __shfl_xor_sync(0xFFFFFFFFu, acc.y, o);
        acc.z += __shfl_xor_sync(0xFFFFFFFFu, acc.z, o);
        acc.w += __shfl_xor_sync(0xFFFFFFFFu, acc.w, o);
    }
#pragma unroll
    for (int o = 16; o > 0; o >>= 1)
        ssum += __shfl_xor_sync(0xFFFFFFFFu, ssum, o);

    if (lane < 8) {
        float inv = 1.0f / ssum;
        float v;
        float4 r;
        v = acc.x * inv; r.x = v > 0.f ? v : expm1f(v);
        v = acc.y * inv; r.y = v > 0.f ? v : expm1f(v);
        v = acc.z * inv; r.z = v > 0.f ? v : expm1f(v);
        v = acc.w * inv; r.w = v > 0.f ? v : expm1f(v);
        op[lane] = r;
    }
}

// ---------------------------------------------------------------------------
extern "C" void kernel_launch(void* const* d_in, const int* in_sizes, int n_in,
                              void* d_out, int out_size)
{
    const float* x  = (const float*)d_in[0];   // (N, 128)
    const float* W  = (const float*)d_in[1];   // (128, 32)
    const float* a  = (const float*)d_in[2];   // (64, 1)
    const int*   ei = (const int*)d_in[3];     // (2, E) int32
    float* out = (float*)d_out;                // (N, 32)

    const int n = in_sizes[0] / FIN;
    const int E = in_sizes[3] / 2;
    const int nb = (n + SCAN_CH - 1) / SCAN_CH;
    const int quads = (E + 3) / 4;

    k_gemm_alpha<<<(n + RB - 1) / RB, 256>>>(x, W, a, n);
    k_hist<<<(quads + 255) / 256, 256>>>(ei, E);
    k_scan1<<<nb, SCAN_CH>>>(n);
    k_scan2<<<1, 256>>>(nb, n, E);
    k_scan3<<<nb, SCAN_CH>>>(n);
    k_scatter<<<(quads + 255) / 256, 256>>>(ei, E);
    k_agg<<<(n * 32 + 255) / 256, 256>>>(out, n);
}